// round 4
// baseline (speedup 1.0000x reference)
#include <cuda_runtime.h>
#include <cuda_bf16.h>
#include <mma.h>

using namespace nvcuda;

// Problem constants
#define K_DIM   49152
#define N_DIM   2048
#define N_WAY   64
#define N_SUP   1024
#define N_QRY   2048
#define M_TOT   (N_WAY + N_QRY)   // 2112
#define EPS_CS  1e-6f

// GEMM tiling
#define BM 128
#define BN 128
#define BK 32
#define LDA 40     // 32 + 8 pad (bf16 elems)
#define LDB 136    // 128 + 8 pad (bf16 elems)

// Scratch (device globals — no cudaMalloc allowed)
__device__ float g_protoA[N_WAY * K_DIM];     // class-mean images  [64, 49152]
__device__ float g_Z[M_TOT * N_DIM];          // embeddings (proto rows 0..63, query rows 64..2111)
__device__ float g_norms[M_TOT];

// ---------------------------------------------------------------------------
// Kernel 1: per-class mean of support images (deterministic row gather)
// grid (64, 16), block 256
// ---------------------------------------------------------------------------
__global__ void proto_mean_kernel(const float* __restrict__ support,
                                  const int* __restrict__ labels) {
    __shared__ int s_rows[N_SUP];
    __shared__ int s_cnt;
    const int c   = blockIdx.x;
    const int tid = threadIdx.x;

    // Warp 0 builds the (deterministically ordered) row list for class c.
    if (tid < 32) {
        int cnt = 0;
        for (int base = 0; base < N_SUP; base += 32) {
            int lab = labels[base + tid];
            unsigned m = __ballot_sync(0xffffffffu, lab == c);
            if (lab == c)
                s_rows[cnt + __popc(m & ((1u << tid) - 1u))] = base + tid;
            cnt += __popc(m);
        }
        if (tid == 0) s_cnt = cnt;
    }
    __syncthreads();

    const int   n   = s_cnt;
    const float inv = 1.0f / (float)n;
    const int kchunk = K_DIM / gridDim.y;           // 3072
    const int k0     = blockIdx.y * kchunk;

    for (int k = k0 + tid; k < k0 + kchunk; k += blockDim.x) {
        float s = 0.0f;
        for (int j = 0; j < n; j++)
            s += support[s_rows[j] * K_DIM + k];
        g_protoA[c * K_DIM + k] = s * inv;
    }
}

// ---------------------------------------------------------------------------
// fp32 -> (hi, lo) bf16 split, 4 elements, vectorized smem store
// ---------------------------------------------------------------------------
__device__ __forceinline__ void storeSplit4(__nv_bfloat16* ph, __nv_bfloat16* pl, float4 v) {
    __nv_bfloat16 h0 = __float2bfloat16(v.x);
    __nv_bfloat16 h1 = __float2bfloat16(v.y);
    __nv_bfloat16 h2 = __float2bfloat16(v.z);
    __nv_bfloat16 h3 = __float2bfloat16(v.w);
    __nv_bfloat16 l0 = __float2bfloat16(v.x - __bfloat162float(h0));
    __nv_bfloat16 l1 = __float2bfloat16(v.y - __bfloat162float(h1));
    __nv_bfloat16 l2 = __float2bfloat16(v.z - __bfloat162float(h2));
    __nv_bfloat16 l3 = __float2bfloat16(v.w - __bfloat162float(h3));
    unsigned h01 = (unsigned)__bfloat16_as_ushort(h0) | ((unsigned)__bfloat16_as_ushort(h1) << 16);
    unsigned h23 = (unsigned)__bfloat16_as_ushort(h2) | ((unsigned)__bfloat16_as_ushort(h3) << 16);
    unsigned l01 = (unsigned)__bfloat16_as_ushort(l0) | ((unsigned)__bfloat16_as_ushort(l1) << 16);
    unsigned l23 = (unsigned)__bfloat16_as_ushort(l2) | ((unsigned)__bfloat16_as_ushort(l3) << 16);
    *reinterpret_cast<uint2*>(ph) = make_uint2(h01, h23);
    *reinterpret_cast<uint2*>(pl) = make_uint2(l01, l23);
}

// ---------------------------------------------------------------------------
// Kernel 2: Z[M_TOT, 2048] = A[M_TOT, K] @ W[K, 2048]   (no bias yet)
// A rows 0..63 = g_protoA, rows 64..2111 = query. 3xBF16 split, fp32 acc.
// grid (16, 17), block 256 (8 warps, 2x4 -> warp tile 64x32)
// ---------------------------------------------------------------------------
__global__ __launch_bounds__(256, 2)
void gemm3_kernel(const float* __restrict__ query,
                  const float* __restrict__ W) {
    __shared__ __nv_bfloat16 As_h[BM * LDA];
    __shared__ __nv_bfloat16 As_l[BM * LDA];
    __shared__ __nv_bfloat16 Bs_h[BK * LDB];
    __shared__ __nv_bfloat16 Bs_l[BK * LDB];

    const int tid = threadIdx.x;
    const int n0  = blockIdx.x * BN;
    const int m0  = blockIdx.y * BM;
    const int warpId = tid >> 5;
    const int wm = warpId >> 2;   // 0..1  (64 rows each)
    const int wn = warpId & 3;    // 0..3  (32 cols each)

    wmma::fragment<wmma::accumulator, 16, 16, 16, float> acc[4][2];
#pragma unroll
    for (int mi = 0; mi < 4; mi++)
#pragma unroll
        for (int ni = 0; ni < 2; ni++)
            wmma::fill_fragment(acc[mi][ni], 0.0f);

    for (int k0 = 0; k0 < K_DIM; k0 += BK) {
        // --- load A tile (128 x 32 fp32), split into hi/lo bf16 ---
#pragma unroll
        for (int j = 0; j < 4; j++) {
            int idx = tid + j * 256;          // 0..1023
            int r   = idx >> 3;               // 0..127
            int c4  = (idx & 7) << 2;         // 0,4,..,28
            int gm  = m0 + r;
            float4 v = make_float4(0.f, 0.f, 0.f, 0.f);
            if (gm < N_WAY)
                v = *reinterpret_cast<const float4*>(&g_protoA[gm * K_DIM + k0 + c4]);
            else if (gm < M_TOT)
                v = *reinterpret_cast<const float4*>(&query[(gm - N_WAY) * K_DIM + k0 + c4]);
            storeSplit4(&As_h[r * LDA + c4], &As_l[r * LDA + c4], v);
        }
        // --- load B tile (32 x 128 fp32), split ---
#pragma unroll
        for (int j = 0; j < 4; j++) {
            int idx = tid + j * 256;          // 0..1023
            int r   = idx >> 5;               // 0..31
            int c4  = (idx & 31) << 2;        // 0,4,..,124
            float4 v = *reinterpret_cast<const float4*>(&W[(k0 + r) * N_DIM + n0 + c4]);
            storeSplit4(&Bs_h[r * LDB + c4], &Bs_l[r * LDB + c4], v);
        }
        __syncthreads();

#pragma unroll
        for (int kk = 0; kk < BK; kk += 16) {
            wmma::fragment<wmma::matrix_a, 16, 16, 16, __nv_bfloat16, wmma::row_major> afrag[4];
            // hi(A) x {hi(B), lo(B)}
#pragma unroll
            for (int mi = 0; mi < 4; mi++)
                wmma::load_matrix_sync(afrag[mi], &As_h[(wm * 64 + mi * 16) * LDA + kk], LDA);
#pragma unroll
            for (int ni = 0; ni < 2; ni++) {
                wmma::fragment<wmma::matrix_b, 16, 16, 16, __nv_bfloat16, wmma::row_major> bfrag;
                wmma::load_matrix_sync(bfrag, &Bs_h[kk * LDB + wn * 32 + ni * 16], LDB);
#pragma unroll
                for (int mi = 0; mi < 4; mi++)
                    wmma::mma_sync(acc[mi][ni], afrag[mi], bfrag, acc[mi][ni]);
                wmma::load_matrix_sync(bfrag, &Bs_l[kk * LDB + wn * 32 + ni * 16], LDB);
#pragma unroll
                for (int mi = 0; mi < 4; mi++)
                    wmma::mma_sync(acc[mi][ni], afrag[mi], bfrag, acc[mi][ni]);
            }
            // lo(A) x hi(B)
#pragma unroll
            for (int mi = 0; mi < 4; mi++)
                wmma::load_matrix_sync(afrag[mi], &As_l[(wm * 64 + mi * 16) * LDA + kk], LDA);
#pragma unroll
            for (int ni = 0; ni < 2; ni++) {
                wmma::fragment<wmma::matrix_b, 16, 16, 16, __nv_bfloat16, wmma::row_major> bfrag;
                wmma::load_matrix_sync(bfrag, &Bs_h[kk * LDB + wn * 32 + ni * 16], LDB);
#pragma unroll
                for (int mi = 0; mi < 4; mi++)
                    wmma::mma_sync(acc[mi][ni], afrag[mi], bfrag, acc[mi][ni]);
            }
        }
        __syncthreads();
    }

    // Epilogue: warp-row block is either fully valid or fully out of range
    // (2112 = 2048 + 64 aligns to the 64-row warp tile).
    const int rowBase = m0 + wm * 64;
    if (rowBase < M_TOT) {
#pragma unroll
        for (int mi = 0; mi < 4; mi++)
#pragma unroll
            for (int ni = 0; ni < 2; ni++)
                wmma::store_matrix_sync(&g_Z[(rowBase + mi * 16) * N_DIM + n0 + wn * 32 + ni * 16],
                                        acc[mi][ni], N_DIM, wmma::mem_row_major);
    }
}

// ---------------------------------------------------------------------------
// Kernel 3: Z[m] += b (in place) and row norms. grid 2112, block 256.
// ---------------------------------------------------------------------------
__global__ void bias_norm_kernel(const float* __restrict__ b) {
    __shared__ float red[256];
    const int m   = blockIdx.x;
    const int tid = threadIdx.x;
    float* z = &g_Z[m * N_DIM];
    float acc = 0.0f;
    for (int k = tid; k < N_DIM; k += 256) {
        float v = z[k] + b[k];
        z[k] = v;
        acc += v * v;
    }
    red[tid] = acc;
    __syncthreads();
    for (int s = 128; s > 0; s >>= 1) {
        if (tid < s) red[tid] += red[tid + s];
        __syncthreads();
    }
    if (tid == 0) g_norms[m] = sqrtf(red[0]);
}

// ---------------------------------------------------------------------------
// Kernel 4: cosine scores. grid 2048 (one query/block), block 256 (8 warps).
// Each warp handles protos c = warp, warp+8, ... with coalesced k access.
// ---------------------------------------------------------------------------
__global__ void scores_kernel(float* __restrict__ out) {
    __shared__ float q[N_DIM];
    const int qi   = blockIdx.x;
    const int tid  = threadIdx.x;
    const int warp = tid >> 5;
    const int lane = tid & 31;

    const float* qrow = &g_Z[(N_WAY + qi) * N_DIM];
    for (int k = tid; k < N_DIM; k += 256) q[k] = qrow[k];
    __syncthreads();

    const float qn = g_norms[N_WAY + qi];
    for (int c = warp; c < N_WAY; c += 8) {
        const float* p = &g_Z[c * N_DIM];
        float acc = 0.0f;
        for (int k = lane; k < N_DIM; k += 32)
            acc += q[k] * p[k];
#pragma unroll
        for (int off = 16; off > 0; off >>= 1)
            acc += __shfl_xor_sync(0xffffffffu, acc, off);
        if (lane == 0) {
            float d = fmaxf(qn * g_norms[c], EPS_CS);
            out[qi * N_WAY + c] = acc / d;
        }
    }
}

// ---------------------------------------------------------------------------
// Launch
// ---------------------------------------------------------------------------
extern "C" void kernel_launch(void* const* d_in, const int* in_sizes, int n_in,
                              void* d_out, int out_size) {
    const float* support = (const float*)d_in[0];   // [1024, 49152] f32
    const int*   labels  = (const int*)  d_in[1];   // [1024] i32
    const float* query   = (const float*)d_in[2];   // [2048, 49152] f32
    const float* W       = (const float*)d_in[3];   // [49152, 2048] f32
    const float* b       = (const float*)d_in[4];   // [2048] f32
    float*       out     = (float*)d_out;           // [2048, 64] f32

    proto_mean_kernel<<<dim3(N_WAY, 16), 256>>>(support, labels);
    gemm3_kernel<<<dim3(N_DIM / BN, (M_TOT + BM - 1) / BM), 256>>>(query, W);
    bias_norm_kernel<<<M_TOT, 256>>>(b);
    scores_kernel<<<N_QRY, 256>>>(out);
}

// round 8
// speedup vs baseline: 1.3922x; 1.3922x over previous
#include <cuda_runtime.h>
#include <cuda_bf16.h>
#include <mma.h>
#include <cstdint>
#include <cstddef>

using namespace nvcuda;

// ---------------------------------------------------------------------------
// Problem constants
// ---------------------------------------------------------------------------
#define K_DIM   49152
#define N_DIM   2048
#define N_WAY   64
#define N_SUP   1024
#define N_QRY   2048
#define M_TOT   2112             // 64 protos + 2048 queries
#define M_PAD   2176             // 17 * 128 (pad rows stay zero)
#define EPS_CS  1e-6f

// GEMM tiling
#define BM 128
#define BN 128
#define BK 32
#define CHUNKS (K_DIM / BK)      // 1536
#define STAGES 3
#define LDA 40                   // 32 + 8 pad (bf16), row = 80B (16B aligned)
#define LDB 136                  // 128 + 8 pad (bf16), row = 272B (16B aligned)

// Per-stage smem byte offsets
#define AH_OFF 0
#define AL_OFF (BM * LDA * 2)                    // 10240
#define BH_OFF (2 * BM * LDA * 2)                // 20480
#define BL_OFF (2 * BM * LDA * 2 + BK * LDB * 2) // 29184
#define STAGE_B (2 * BM * LDA * 2 + 2 * BK * LDB * 2)   // 37888
#define DSMEM_BYTES (STAGES * STAGE_B)                  // 113664

// ---------------------------------------------------------------------------
// Device scratch (no cudaMalloc allowed; globals are zero-initialized)
// ---------------------------------------------------------------------------
__device__ __align__(16)  float         g_protoA[N_WAY * K_DIM];
__device__ __align__(16)  float         g_Z[M_TOT * N_DIM];
__device__                float         g_norms[M_TOT];
__device__ __align__(128) __nv_bfloat16 g_Xh[(size_t)M_PAD * K_DIM];
__device__ __align__(128) __nv_bfloat16 g_Xl[(size_t)M_PAD * K_DIM];
__device__ __align__(128) __nv_bfloat16 g_Wh[(size_t)K_DIM * N_DIM];
__device__ __align__(128) __nv_bfloat16 g_Wl[(size_t)K_DIM * N_DIM];

// ---------------------------------------------------------------------------
// Helpers
// ---------------------------------------------------------------------------
__device__ __forceinline__ uint32_t smem_u32(const void* p) {
    uint32_t a;
    asm("{ .reg .u64 t; cvta.to.shared.u64 t, %1; cvt.u32.u64 %0, t; }" : "=r"(a) : "l"(p));
    return a;
}
__device__ __forceinline__ void cp_async16(uint32_t dst, const void* src) {
    asm volatile("cp.async.cg.shared.global [%0], [%1], 16;" :: "r"(dst), "l"(src) : "memory");
}
__device__ __forceinline__ void cp_commit() {
    asm volatile("cp.async.commit_group;" ::: "memory");
}
template <int N>
__device__ __forceinline__ void cp_wait() {
    asm volatile("cp.async.wait_group %0;" :: "n"(N) : "memory");
}

// f32x4 -> packed hi bf16x4 (8B) + residual float4
__device__ __forceinline__ unsigned long long pack4_hi(float4 v, float4* rem) {
    __nv_bfloat16 h0 = __float2bfloat16(v.x), h1 = __float2bfloat16(v.y);
    __nv_bfloat16 h2 = __float2bfloat16(v.z), h3 = __float2bfloat16(v.w);
    rem->x = v.x - __bfloat162float(h0);
    rem->y = v.y - __bfloat162float(h1);
    rem->z = v.z - __bfloat162float(h2);
    rem->w = v.w - __bfloat162float(h3);
    unsigned a = (unsigned)__bfloat16_as_ushort(h0) | ((unsigned)__bfloat16_as_ushort(h1) << 16);
    unsigned b = (unsigned)__bfloat16_as_ushort(h2) | ((unsigned)__bfloat16_as_ushort(h3) << 16);
    return (unsigned long long)a | ((unsigned long long)b << 32);
}
__device__ __forceinline__ unsigned long long pack4(float4 v) {
    __nv_bfloat16 h0 = __float2bfloat16(v.x), h1 = __float2bfloat16(v.y);
    __nv_bfloat16 h2 = __float2bfloat16(v.z), h3 = __float2bfloat16(v.w);
    unsigned a = (unsigned)__bfloat16_as_ushort(h0) | ((unsigned)__bfloat16_as_ushort(h1) << 16);
    unsigned b = (unsigned)__bfloat16_as_ushort(h2) | ((unsigned)__bfloat16_as_ushort(h3) << 16);
    return (unsigned long long)a | ((unsigned long long)b << 32);
}

// ---------------------------------------------------------------------------
// Kernel 1: per-class mean of support images. grid (64, 16), block 256
// ---------------------------------------------------------------------------
__global__ void proto_mean_kernel(const float* __restrict__ support,
                                  const int* __restrict__ labels) {
    __shared__ int s_rows[N_SUP];
    __shared__ int s_cnt;
    const int c   = blockIdx.x;
    const int tid = threadIdx.x;

    if (tid < 32) {
        int cnt = 0;
        for (int base = 0; base < N_SUP; base += 32) {
            int lab = labels[base + tid];
            unsigned m = __ballot_sync(0xffffffffu, lab == c);
            if (lab == c)
                s_rows[cnt + __popc(m & ((1u << tid) - 1u))] = base + tid;
            cnt += __popc(m);
        }
        if (tid == 0) s_cnt = cnt;
    }
    __syncthreads();

    const int   n   = s_cnt;
    const float inv = 1.0f / (float)n;
    const int kchunk = K_DIM / gridDim.y;
    const int k0     = blockIdx.y * kchunk;

    for (int k = k0 + tid; k < k0 + kchunk; k += blockDim.x) {
        float s = 0.0f;
        for (int j = 0; j < n; j++)
            s += support[(size_t)s_rows[j] * K_DIM + k];
        g_protoA[c * K_DIM + k] = s * inv;
    }
}

// ---------------------------------------------------------------------------
// Kernel 2: split-convert X rows (protos first, then queries). grid 2112.
// ---------------------------------------------------------------------------
__global__ void convert_X_kernel(const float* __restrict__ query) {
    const int row = blockIdx.x;
    const float* src = (row < N_WAY) ? &g_protoA[(size_t)row * K_DIM]
                                     : &query[(size_t)(row - N_WAY) * K_DIM];
    __nv_bfloat16* dh = &g_Xh[(size_t)row * K_DIM];
    __nv_bfloat16* dl = &g_Xl[(size_t)row * K_DIM];
    for (int k4 = threadIdx.x * 4; k4 < K_DIM; k4 += blockDim.x * 4) {
        float4 v = *reinterpret_cast<const float4*>(&src[k4]);
        float4 rem;
        unsigned long long hi = pack4_hi(v, &rem);
        unsigned long long lo = pack4(rem);
        *reinterpret_cast<unsigned long long*>(&dh[k4]) = hi;
        *reinterpret_cast<unsigned long long*>(&dl[k4]) = lo;
    }
}

// ---------------------------------------------------------------------------
// Kernel 3: split-convert W (flat, layout preserved). grid 98304, block 256.
// ---------------------------------------------------------------------------
__global__ void convert_W_kernel(const float* __restrict__ W) {
    const size_t i4 = ((size_t)blockIdx.x * blockDim.x + threadIdx.x) * 4;
    float4 v = *reinterpret_cast<const float4*>(&W[i4]);
    float4 rem;
    unsigned long long hi = pack4_hi(v, &rem);
    unsigned long long lo = pack4(rem);
    *reinterpret_cast<unsigned long long*>(&g_Wh[i4]) = hi;
    *reinterpret_cast<unsigned long long*>(&g_Wl[i4]) = lo;
}

// ---------------------------------------------------------------------------
// Kernel 4: GEMM  Z[M_PAD, 2048] = X @ W  (3xbf16 split, f32 acc)
// grid (16 n-tiles, 17 m-tiles), block 256, 3-stage cp.async pipeline.
// ---------------------------------------------------------------------------
__device__ __forceinline__ void issue_stage(int c, int stage, int m0, int n0,
                                            int tid, uint32_t smem_base) {
    const int k0 = c * BK;
    const uint32_t sb = smem_base + (uint32_t)stage * STAGE_B;
    // A tiles: 128 rows x 32 cols bf16 = 4 x 16B per row, x2 matrices
#pragma unroll
    for (int i = 0; i < 2; i++) {
        int idx = tid + i * 256;            // 0..511
        int r   = idx >> 2;                 // 0..127
        int seg = (idx & 3) * 8;            // bf16 elems (16B segs)
        uint32_t doff = (uint32_t)(r * LDA + seg) * 2u;
        cp_async16(sb + AH_OFF + doff, &g_Xh[(size_t)(m0 + r) * K_DIM + k0 + seg]);
        cp_async16(sb + AL_OFF + doff, &g_Xl[(size_t)(m0 + r) * K_DIM + k0 + seg]);
    }
    // B tiles: 32 rows x 128 cols bf16 = 16 x 16B per row, x2 matrices
#pragma unroll
    for (int i = 0; i < 2; i++) {
        int idx = tid + i * 256;            // 0..511
        int r   = idx >> 4;                 // 0..31
        int seg = (idx & 15) * 8;
        uint32_t doff = (uint32_t)(r * LDB + seg) * 2u;
        cp_async16(sb + BH_OFF + doff, &g_Wh[(size_t)(k0 + r) * N_DIM + n0 + seg]);
        cp_async16(sb + BL_OFF + doff, &g_Wl[(size_t)(k0 + r) * N_DIM + n0 + seg]);
    }
    cp_commit();
}

__global__ void __launch_bounds__(256, 2) gemm_wmma_kernel() {
    extern __shared__ char dsm[];
    const uint32_t smem_base = smem_u32(dsm);

    const int tid = threadIdx.x;
    const int n0  = blockIdx.x * BN;
    const int m0  = blockIdx.y * BM;
    const int warpId = tid >> 5;
    const int wm = warpId >> 2;   // 0..1 (64 rows)
    const int wn = warpId & 3;    // 0..3 (32 cols)

    wmma::fragment<wmma::accumulator, 16, 16, 16, float> acc[4][2];
#pragma unroll
    for (int mi = 0; mi < 4; mi++)
#pragma unroll
        for (int ni = 0; ni < 2; ni++)
            wmma::fill_fragment(acc[mi][ni], 0.0f);

    // prologue: 2 stages in flight
    issue_stage(0, 0, m0, n0, tid, smem_base);
    issue_stage(1, 1, m0, n0, tid, smem_base);

    int stage = 0;
    for (int c = 0; c < CHUNKS; c++) {
        cp_wait<1>();
        __syncthreads();

        if (c + 2 < CHUNKS)
            issue_stage(c + 2, (stage + 2) % STAGES, m0, n0, tid, smem_base);

        const char* sb = dsm + stage * STAGE_B;
        const __nv_bfloat16* Ah = (const __nv_bfloat16*)(sb + AH_OFF);
        const __nv_bfloat16* Al = (const __nv_bfloat16*)(sb + AL_OFF);
        const __nv_bfloat16* Bh = (const __nv_bfloat16*)(sb + BH_OFF);
        const __nv_bfloat16* Bl = (const __nv_bfloat16*)(sb + BL_OFF);

#pragma unroll
        for (int kk = 0; kk < BK; kk += 16) {
            wmma::fragment<wmma::matrix_a, 16, 16, 16, __nv_bfloat16, wmma::row_major> ah[4], al[4];
#pragma unroll
            for (int mi = 0; mi < 4; mi++) {
                wmma::load_matrix_sync(ah[mi], &Ah[(wm * 64 + mi * 16) * LDA + kk], LDA);
                wmma::load_matrix_sync(al[mi], &Al[(wm * 64 + mi * 16) * LDA + kk], LDA);
            }
#pragma unroll
            for (int ni = 0; ni < 2; ni++) {
                wmma::fragment<wmma::matrix_b, 16, 16, 16, __nv_bfloat16, wmma::row_major> bh, bl;
                wmma::load_matrix_sync(bh, &Bh[kk * LDB + wn * 32 + ni * 16], LDB);
                wmma::load_matrix_sync(bl, &Bl[kk * LDB + wn * 32 + ni * 16], LDB);
#pragma unroll
                for (int mi = 0; mi < 4; mi++) {
                    wmma::mma_sync(acc[mi][ni], ah[mi], bh, acc[mi][ni]);
                    wmma::mma_sync(acc[mi][ni], ah[mi], bl, acc[mi][ni]);
                    wmma::mma_sync(acc[mi][ni], al[mi], bh, acc[mi][ni]);
                }
            }
        }
        __syncthreads();
        stage = (stage + 1) % STAGES;
    }

    // epilogue: 64-row warp blocks are fully valid or fully padding
    const int rowBase = m0 + wm * 64;
    if (rowBase < M_TOT) {
#pragma unroll
        for (int mi = 0; mi < 4; mi++)
#pragma unroll
            for (int ni = 0; ni < 2; ni++)
                wmma::store_matrix_sync(&g_Z[(size_t)(rowBase + mi * 16) * N_DIM + n0 + wn * 32 + ni * 16],
                                        acc[mi][ni], N_DIM, wmma::mem_row_major);
    }
}

// ---------------------------------------------------------------------------
// Kernel 5: Z += b (in place) and row norms. grid 2112, block 256.
// ---------------------------------------------------------------------------
__global__ void bias_norm_kernel(const float* __restrict__ b) {
    __shared__ float red[256];
    const int m   = blockIdx.x;
    const int tid = threadIdx.x;
    float* z = &g_Z[(size_t)m * N_DIM];
    float acc = 0.0f;
    for (int k = tid; k < N_DIM; k += 256) {
        float v = z[k] + b[k];
        z[k] = v;
        acc += v * v;
    }
    red[tid] = acc;
    __syncthreads();
    for (int s = 128; s > 0; s >>= 1) {
        if (tid < s) red[tid] += red[tid + s];
        __syncthreads();
    }
    if (tid == 0) g_norms[m] = sqrtf(red[0]);
}

// ---------------------------------------------------------------------------
// Kernel 6: cosine scores. grid 2048, block 256.
// ---------------------------------------------------------------------------
__global__ void scores_kernel(float* __restrict__ out) {
    __shared__ float q[N_DIM];
    const int qi   = blockIdx.x;
    const int tid  = threadIdx.x;
    const int warp = tid >> 5;
    const int lane = tid & 31;

    const float* qrow = &g_Z[(size_t)(N_WAY + qi) * N_DIM];
    for (int k = tid; k < N_DIM; k += 256) q[k] = qrow[k];
    __syncthreads();

    const float qn = g_norms[N_WAY + qi];
    for (int c = warp; c < N_WAY; c += 8) {
        const float* p = &g_Z[(size_t)c * N_DIM];
        float acc = 0.0f;
        for (int k = lane; k < N_DIM; k += 32)
            acc += q[k] * p[k];
#pragma unroll
        for (int off = 16; off > 0; off >>= 1)
            acc += __shfl_xor_sync(0xffffffffu, acc, off);
        if (lane == 0) {
            float d = fmaxf(qn * g_norms[c], EPS_CS);
            out[qi * N_WAY + c] = acc / d;
        }
    }
}

// ---------------------------------------------------------------------------
// Launch
// ---------------------------------------------------------------------------
extern "C" void kernel_launch(void* const* d_in, const int* in_sizes, int n_in,
                              void* d_out, int out_size) {
    const float* support = (const float*)d_in[0];   // [1024, 49152] f32
    const int*   labels  = (const int*)  d_in[1];   // [1024] i32
    const float* query   = (const float*)d_in[2];   // [2048, 49152] f32
    const float* W       = (const float*)d_in[3];   // [49152, 2048] f32
    const float* b       = (const float*)d_in[4];   // [2048] f32
    float*       out     = (float*)d_out;           // [2048, 64] f32

    cudaFuncSetAttribute(gemm_wmma_kernel,
                         cudaFuncAttributeMaxDynamicSharedMemorySize, DSMEM_BYTES);

    proto_mean_kernel<<<dim3(N_WAY, 16), 256>>>(support, labels);
    convert_X_kernel<<<M_TOT, 256>>>(query);
    convert_W_kernel<<<(K_DIM / 4) * (N_DIM / 256), 256>>>(W);
    gemm_wmma_kernel<<<dim3(N_DIM / BN, M_PAD / BM), 256, DSMEM_BYTES>>>();
    bias_norm_kernel<<<M_TOT, 256>>>(b);
    scores_kernel<<<N_QRY, 256>>>(out);
}